// round 3
// baseline (speedup 1.0000x reference)
#include <cuda_runtime.h>
#include <cstdint>

// OptFP_Embedding: out[b,f,:] = beta + sum_i c_i(g) * clip(rint(W*ia_i - beta*ia_i), lo_i, hi_i)
//   c_i = softmax(gamma)_i * (|alpha_i|+eps); sum_i softmax = 1 folds beta into the output.
//
// Inputs (metadata order):
//   d_in[0] = x           int32   [4096*39]
//   d_in[1] = weight      float32 [1000000*64]
//   d_in[2] = group_index int32   [1000000]
//   d_in[3] = gamma       float32 [8*1*3]
//   d_in[4] = alpha       float32 [3]
//   d_in[5] = beta        float32 [64]
// Output: float32 [4096*39*64]

#define EMB_DIM 64
#define GROUPS 8
#define NBITS 3
#define TPT 16                 // threads per token (16 x float4 = 64 floats)
#define BLOCK_THREADS 256
#define SUBS (BLOCK_THREADS / TPT)      // 16 token slots per pass
#define TOK_PER_THREAD 8                // 8 independent row gathers in flight per thread
#define TOKENS_PER_BLOCK (SUBS * TOK_PER_THREAD)   // 128

__global__ __launch_bounds__(BLOCK_THREADS, 4)
void optfp_embedding_kernel(const int* __restrict__ x,
                            const float* __restrict__ weight,
                            const int* __restrict__ group_index,
                            const float* __restrict__ gamma,
                            const float* __restrict__ alpha,
                            const float* __restrict__ beta,
                            float* __restrict__ out,
                            int ntok) {
    __shared__ float s_beta[EMB_DIM];
    __shared__ float s_nbia[NBITS][EMB_DIM];  // -beta[e] * ia_i
    __shared__ float s_c[GROUPS][NBITS];      // softmax(gamma)_i * a_i
    __shared__ float s_ia[NBITS];             // 1 / (|alpha_i| + eps)

    const int tid = threadIdx.x;
    if (tid < NBITS) {
        float a = fabsf(alpha[tid]) + 1e-10f;
        s_ia[tid] = 1.0f / a;
    }
    if (tid < GROUPS) {
        // TAU = 1.0
        float g0 = gamma[tid * NBITS + 0];
        float g1 = gamma[tid * NBITS + 1];
        float g2 = gamma[tid * NBITS + 2];
        float m = fmaxf(g0, fmaxf(g1, g2));
        float e0 = __expf(g0 - m);
        float e1 = __expf(g1 - m);
        float e2 = __expf(g2 - m);
        float inv = 1.0f / (e0 + e1 + e2);
        s_c[tid][0] = e0 * inv * (fabsf(alpha[0]) + 1e-10f);
        s_c[tid][1] = e1 * inv * (fabsf(alpha[1]) + 1e-10f);
        s_c[tid][2] = e2 * inv * (fabsf(alpha[2]) + 1e-10f);
    }
    __syncthreads();            // s_ia ready before s_nbia computed
    if (tid < EMB_DIM) {
        float b = beta[tid];
        s_beta[tid] = b;
        s_nbia[0][tid] = -b * s_ia[0];
        s_nbia[1][tid] = -b * s_ia[1];
        s_nbia[2][tid] = -b * s_ia[2];
    }
    __syncthreads();

    const int sub  = tid >> 4;            // 0..15
    const int lane = tid & (TPT - 1);     // 0..15

    const unsigned base = (unsigned)blockIdx.x * TOKENS_PER_BLOCK + sub;

    // ---- Front-batched independent loads ----
    unsigned tok[TOK_PER_THREAD];
    bool valid[TOK_PER_THREAD];
    int idx[TOK_PER_THREAD];
#pragma unroll
    for (int k = 0; k < TOK_PER_THREAD; k++) {
        tok[k]   = base + (unsigned)k * SUBS;
        valid[k] = tok[k] < (unsigned)ntok;
        idx[k]   = valid[k] ? __ldg(x + tok[k]) : 0;
    }

    int g[TOK_PER_THREAD];
    float4 w[TOK_PER_THREAD];
#pragma unroll
    for (int k = 0; k < TOK_PER_THREAD; k++) {
        g[k] = __ldg(group_index + idx[k]);
        // 32-bit element offset: idx*16 float4 units (max 16M, fits u32)
        w[k] = __ldg((const float4*)weight + (((unsigned)idx[k]) << 4) + lane);
    }

    const float4 b4  = ((const float4*)s_beta)[lane];
    const float4 n0  = ((const float4*)s_nbia[0])[lane];
    const float4 n1  = ((const float4*)s_nbia[1])[lane];
    const float4 n2  = ((const float4*)s_nbia[2])[lane];
    const float ia0 = s_ia[0], ia1 = s_ia[1], ia2 = s_ia[2];

#pragma unroll
    for (int k = 0; k < TOK_PER_THREAD; k++) {
        if (!valid[k]) continue;
        const float c0 = s_c[g[k]][0];
        const float c1 = s_c[g[k]][1];
        const float c2 = s_c[g[k]][2];

        const float wv[4] = {w[k].x, w[k].y, w[k].z, w[k].w};
        const float bv[4] = {b4.x, b4.y, b4.z, b4.w};
        const float n0v[4] = {n0.x, n0.y, n0.z, n0.w};
        const float n1v[4] = {n1.x, n1.y, n1.z, n1.w};
        const float n2v[4] = {n2.x, n2.y, n2.z, n2.w};
        float rv[4];
#pragma unroll
        for (int c = 0; c < 4; c++) {
            // wa_i = w*ia_i - beta*ia_i  (single FMA each)
            const float r0 = fminf(fmaxf(rintf(fmaf(wv[c], ia0, n0v[c])),   -2.0f),   1.0f);
            const float r1 = fminf(fmaxf(rintf(fmaf(wv[c], ia1, n1v[c])),   -8.0f),   7.0f);
            const float r2 = fminf(fmaxf(rintf(fmaf(wv[c], ia2, n2v[c])), -128.0f), 127.0f);
            float acc = fmaf(c0, r0, bv[c]);
            acc = fmaf(c1, r1, acc);
            rv[c] = fmaf(c2, r2, acc);
        }
        float4 r; r.x = rv[0]; r.y = rv[1]; r.z = rv[2]; r.w = rv[3];
        __stcs((float4*)out + tok[k] * TPT + lane, r);
    }
}

extern "C" void kernel_launch(void* const* d_in, const int* in_sizes, int n_in,
                              void* d_out, int out_size) {
    const int*   x           = (const int*)d_in[0];
    const float* weight      = (const float*)d_in[1];
    const int*   group_index = (const int*)d_in[2];
    const float* gamma       = (const float*)d_in[3];
    const float* alpha       = (const float*)d_in[4];
    const float* beta        = (const float*)d_in[5];
    float* out = (float*)d_out;

    const int ntok = in_sizes[0];  // 4096 * 39 = 159744
    const int blocks = (ntok + TOKENS_PER_BLOCK - 1) / TOKENS_PER_BLOCK;
    optfp_embedding_kernel<<<blocks, BLOCK_THREADS>>>(
        x, weight, group_index, gamma, alpha, beta, out, ntok);
}

// round 5
// speedup vs baseline: 1.2403x; 1.2403x over previous
#include <cuda_runtime.h>
#include <cuda_pipeline.h>
#include <cstdint>

// OptFP_Embedding: out[b,f,:] = beta + sum_i c_i(g) * clip(rint((W[x]-beta)*ia_i), lo_i, hi_i)
//   c_i = softmax(gamma)_i * (|alpha_i|+eps); sum_i softmax = 1 folds beta out.
//
// Strategy: cp.async (LDGSTS) stages row gathers into SMEM at pipeline depth 8.
// Each thread copies AND consumes the same 16B slot -> no __syncthreads in the
// pipeline; per-thread cp.async wait_group is the only ordering needed.
// Payload never touches the register file -> depth-8 MLP at ~40 regs.
//
// Inputs (metadata order):
//   d_in[0] = x           int32   [4096*39]
//   d_in[1] = weight      float32 [1000000*64]
//   d_in[2] = group_index int32   [1000000]
//   d_in[3] = gamma       float32 [8*1*3]
//   d_in[4] = alpha       float32 [3]
//   d_in[5] = beta        float32 [64]
// Output: float32 [4096*39*64]

#define EMB_DIM 64
#define GROUPS 8
#define NBITS 3
#define TPT 16                    // threads per token (16 x float4 = 64 floats)
#define BLOCK_THREADS 256
#define SUBS (BLOCK_THREADS / TPT)        // 16 tokens per stage
#define STAGES 8                          // cp.async pipeline depth
#define TOKENS_PER_BLOCK (SUBS * STAGES)  // 128

__global__ __launch_bounds__(BLOCK_THREADS)
void optfp_embedding_kernel(const int* __restrict__ x,
                            const float* __restrict__ weight,
                            const int* __restrict__ group_index,
                            const float* __restrict__ gamma,
                            const float* __restrict__ alpha,
                            const float* __restrict__ beta,
                            float* __restrict__ out,
                            int ntok) {
    __shared__ float4 s_rows[STAGES][BLOCK_THREADS];   // 32 KB staging
    __shared__ float s_beta[EMB_DIM];
    __shared__ float s_c[GROUPS][NBITS];    // softmax(gamma)_i * (|alpha_i|+eps)
    __shared__ float s_ia[NBITS];           // 1 / (|alpha_i| + eps)

    const int tid = threadIdx.x;

    // ---- one-time coefficient tables ----
    if (tid < EMB_DIM) s_beta[tid] = beta[tid];
    if (tid < GROUPS) {
        // TAU = 1.0
        float g0 = gamma[tid * NBITS + 0];
        float g1 = gamma[tid * NBITS + 1];
        float g2 = gamma[tid * NBITS + 2];
        float m = fmaxf(g0, fmaxf(g1, g2));
        float e0 = __expf(g0 - m);
        float e1 = __expf(g1 - m);
        float e2 = __expf(g2 - m);
        float inv = 1.0f / (e0 + e1 + e2);
        s_c[tid][0] = e0 * inv * (fabsf(alpha[0]) + 1e-10f);
        s_c[tid][1] = e1 * inv * (fabsf(alpha[1]) + 1e-10f);
        s_c[tid][2] = e2 * inv * (fabsf(alpha[2]) + 1e-10f);
        if (tid == 0) {
            s_ia[0] = 1.0f / (fabsf(alpha[0]) + 1e-10f);
            s_ia[1] = 1.0f / (fabsf(alpha[1]) + 1e-10f);
            s_ia[2] = 1.0f / (fabsf(alpha[2]) + 1e-10f);
        }
    }

    const int sub  = tid >> 4;            // 0..15 : token slot within a stage
    const int lane = tid & (TPT - 1);     // 0..15 : 16B chunk within a row

    const unsigned base = (unsigned)blockIdx.x * TOKENS_PER_BLOCK + sub;

    // ---- prologue: front-batched index gathers ----
    int idx[STAGES];
    bool valid[STAGES];
#pragma unroll
    for (int s = 0; s < STAGES; s++) {
        const unsigned tok = base + (unsigned)s * SUBS;
        valid[s] = tok < (unsigned)ntok;
        idx[s]   = valid[s] ? __ldg(x + tok) : 0;
    }

    int g[STAGES];
#pragma unroll
    for (int s = 0; s < STAGES; s++)
        g[s] = __ldg(group_index + idx[s]);

    // Table visibility barrier BEFORE staging traffic starts, so the barrier's
    // STS-drain doesn't serialize against 2048 in-flight LDGSTS per block.
    __syncthreads();

    // ---- issue depth-8 cp.async row gathers (16B per thread per stage) ----
#pragma unroll
    for (int s = 0; s < STAGES; s++) {
        __pipeline_memcpy_async(&s_rows[s][tid],
                                (const float4*)weight + (((unsigned)idx[s]) << 4) + lane,
                                sizeof(float4));
        __pipeline_commit();
    }

    const float4 b4 = ((const float4*)s_beta)[lane];
    const float ia0 = s_ia[0], ia1 = s_ia[1], ia2 = s_ia[2];

    // ---- drain pipeline: compute one stage as each copy lands ----
#pragma unroll
    for (int s = 0; s < STAGES; s++) {
        __pipeline_wait_prior(STAGES - 1 - s);
        if (!valid[s]) continue;

        const float4 w = s_rows[s][tid];
        const float c0 = s_c[g[s]][0];
        const float c1 = s_c[g[s]][1];
        const float c2 = s_c[g[s]][2];

        const float wv[4] = {w.x, w.y, w.z, w.w};
        const float bv[4] = {b4.x, b4.y, b4.z, b4.w};
        float rv[4];
#pragma unroll
        for (int c = 0; c < 4; c++) {
            const float wb = wv[c] - bv[c];
            const float r0 = fminf(fmaxf(rintf(wb * ia0),   -2.0f),   1.0f);
            const float r1 = fminf(fmaxf(rintf(wb * ia1),   -8.0f),   7.0f);
            const float r2 = fminf(fmaxf(rintf(wb * ia2), -128.0f), 127.0f);
            float acc = fmaf(c0, r0, bv[c]);
            acc = fmaf(c1, r1, acc);
            rv[c] = fmaf(c2, r2, acc);
        }
        float4 r; r.x = rv[0]; r.y = rv[1]; r.z = rv[2]; r.w = rv[3];
        const unsigned tok = base + (unsigned)s * SUBS;
        __stcs((float4*)out + tok * TPT + lane, r);
    }
}

extern "C" void kernel_launch(void* const* d_in, const int* in_sizes, int n_in,
                              void* d_out, int out_size) {
    const int*   x           = (const int*)d_in[0];
    const float* weight      = (const float*)d_in[1];
    const int*   group_index = (const int*)d_in[2];
    const float* gamma       = (const float*)d_in[3];
    const float* alpha       = (const float*)d_in[4];
    const float* beta        = (const float*)d_in[5];
    float* out = (float*)d_out;

    const int ntok = in_sizes[0];  // 4096 * 39 = 159744 = 1248 * 128
    const int blocks = (ntok + TOKENS_PER_BLOCK - 1) / TOKENS_PER_BLOCK;
    optfp_embedding_kernel<<<blocks, BLOCK_THREADS>>>(
        x, weight, group_index, gamma, alpha, beta, out, ntok);
}